// round 2
// baseline (speedup 1.0000x reference)
#include <cuda_runtime.h>
#include <math.h>

#define LL 256
#define MAXB 512

// ---- scratch (device globals: allocation-free, graph-safe) ----
__device__ float g_sumYp[MAXB];
__device__ float g_sumYgYp[MAXB];
__device__ int   g_anyYg[MAXB];
__device__ unsigned char g_rowflag[MAXB][LL];
__device__ unsigned char g_colflag[MAXB][LL];
__device__ float g_ratio[MAXB];

// =====================================================================
// Kernel 1: one block per sample. Single streaming pass over Yp and Yg.
// Extracts: sum(Yp), sum(Yg*Yp), any(Yg>0), row/col "any Yp>0.5" flags.
// =====================================================================
__global__ void __launch_bounds__(512) k1_scan(const float* __restrict__ Yp,
                                               const float* __restrict__ Yg)
{
    const int b = blockIdx.x;
    const int t = threadIdx.x;
    const float4* __restrict__ p4 = (const float4*)(Yp + (size_t)b * LL * LL);
    const float4* __restrict__ g4 = (const float4*)(Yg + (size_t)b * LL * LL);

    __shared__ unsigned char rflag[LL];
    __shared__ unsigned char cflag[LL];
    __shared__ float s1[16], s2[16];
    __shared__ int   s3[16];

    if (t < LL) { rflag[t] = 0; cflag[t] = 0; }
    __syncthreads();

    float sp = 0.f, spg = 0.f;
    int any = 0;

    const int NV = LL * LL / 4;  // 16384 float4 per map
    #pragma unroll 4
    for (int i = t; i < NV; i += 512) {
        float4 v = p4[i];
        float4 g = g4[i];
        sp  += (v.x + v.y) + (v.z + v.w);
        spg += g.x * v.x + g.y * v.y + g.z * v.z + g.w * v.w;
        if (g.x > 0.f || g.y > 0.f || g.z > 0.f || g.w > 0.f) any = 1;

        bool f0 = v.x > 0.5f, f1 = v.y > 0.5f, f2 = v.z > 0.5f, f3 = v.w > 0.5f;
        if (f0 | f1 | f2 | f3) {
            int pix = i << 2;
            int row = pix >> 8;
            int c0  = pix & 255;
            rflag[row] = 1;
            if (f0) cflag[c0]     = 1;
            if (f1) cflag[c0 + 1] = 1;
            if (f2) cflag[c0 + 2] = 1;
            if (f3) cflag[c0 + 3] = 1;
        }
    }

    // block reduction
    const unsigned full = 0xffffffffu;
    #pragma unroll
    for (int o = 16; o > 0; o >>= 1) {
        sp  += __shfl_down_sync(full, sp, o);
        spg += __shfl_down_sync(full, spg, o);
    }
    any = __any_sync(full, any);
    int warp = t >> 5, lane = t & 31;
    if (lane == 0) { s1[warp] = sp; s2[warp] = spg; s3[warp] = any; }
    __syncthreads();
    if (warp == 0) {
        float a = (lane < 16) ? s1[lane] : 0.f;
        float c = (lane < 16) ? s2[lane] : 0.f;
        int  an = (lane < 16) ? s3[lane] : 0;
        #pragma unroll
        for (int o = 8; o > 0; o >>= 1) {
            a += __shfl_down_sync(full, a, o);
            c += __shfl_down_sync(full, c, o);
        }
        an = __any_sync(full, an);
        if (lane == 0) {
            g_sumYp[b]   = a;
            g_sumYgYp[b] = c;
            g_anyYg[b]   = an;
        }
    }
    __syncthreads();
    if (t < LL) {
        g_rowflag[b][t] = rflag[t];
        g_colflag[b][t] = cflag[t];
    }
}

// =====================================================================
// Kernel 2: one block per sample (256 threads). Box from flags; for the
// generated-mask branch, evaluate the exact reference mask over the only
// window where it can be nonzero, summing Yp there. Emit ratio.
// =====================================================================
__global__ void __launch_bounds__(256) k2_ratio(const float* __restrict__ Yp)
{
    const int b = blockIdx.x;
    const int t = threadIdx.x;

    __shared__ int sMinR, sMaxR, sMinC, sMaxC;
    __shared__ float sw[8];

    if (t == 0) { sMinR = LL; sMaxR = -1; sMinC = LL; sMaxC = -1; }
    __syncthreads();
    if (g_rowflag[b][t]) { atomicMin(&sMinR, t); atomicMax(&sMaxR, t); }
    if (g_colflag[b][t]) { atomicMin(&sMinC, t); atomicMax(&sMaxC, t); }
    __syncthreads();

    const float sumYp = g_sumYp[b];
    float positive;

    if (g_anyYg[b]) {
        positive = g_sumYgYp[b];
    } else {
        // box (argmax semantics: all-false -> index 0)
        int left, right, up, down;
        if (sMaxR < 0) { left = 0; right = 0; }
        else           { left = sMinR; right = (LL - 1) - sMaxR; }
        if (sMaxC < 0) { up = 0; down = 0; }
        else           { up = sMinC; down = (LL - 1) - sMaxC; }
        int x_r = (right - left) >> 1;  // floor division, matches //2
        int y_r = (down  - up)   >> 1;
        float gt0 = (float)(left + x_r);  // compared vs column coord
        float gt1 = (float)(up   + y_r);  // compared vs row coord

        float acc = 0.f;
        if (x_r != 0 && y_r != 0) {
            // h>0.1  <=>  d0^4 + d1^4 < ln(10)*(4/9) ~= 1.02337
            // => |d0|,|d1| < 1.00579 ; pad window for safety
            float hx = fabsf((float)x_r) * 1.01f + 1.5f;  // column half-extent
            float hy = fabsf((float)y_r) * 1.01f + 1.5f;  // row half-extent
            int c0 = max(0, (int)floorf(gt0 - hx));
            int c1 = min(LL - 1, (int)ceilf(gt0 + hx));
            int r0 = max(0, (int)floorf(gt1 - hy));
            int r1 = min(LL - 1, (int)ceilf(gt1 + hy));
            int W = c1 - c0 + 1;
            int n = W * (r1 - r0 + 1);
            const float denom = 0.44444445f;  // f32((2*(1/3))^2)
            const float* __restrict__ base = Yp + (size_t)b * LL * LL;
            for (int i = t; i < n; i += 256) {
                int r = r0 + i / W;
                int c = c0 + i % W;
                float d0 = ((float)c - gt0) / (float)x_r;
                float d1 = ((float)r - gt1) / (float)y_r;
                float d02 = d0 * d0, d12 = d1 * d1;
                float s = d02 * d02 + d12 * d12;
                float h = expf(-s / denom);
                if (h > 0.1f) acc += base[r * LL + c];
            }
        }
        // reduce acc across 256 threads
        const unsigned full = 0xffffffffu;
        #pragma unroll
        for (int o = 16; o > 0; o >>= 1) acc += __shfl_down_sync(full, acc, o);
        int warp = t >> 5, lane = t & 31;
        if (lane == 0) sw[warp] = acc;
        __syncthreads();
        float tot = 0.f;
        if (t == 0) {
            #pragma unroll
            for (int w = 0; w < 8; w++) tot += sw[w];
        }
        positive = tot;
    }

    if (t == 0) {
        float negative = sumYp - positive;
        g_ratio[b] = negative / (positive + 1e-6f);
    }
}

// =====================================================================
// Kernel 3: final reduction of B ratios -> log(total)/B (0 if total==0)
// =====================================================================
__global__ void __launch_bounds__(512) k3_final(float* __restrict__ out, int B)
{
    const int t = threadIdx.x;
    __shared__ float sw[16];
    float v = (t < B) ? g_ratio[t] : 0.f;
    const unsigned full = 0xffffffffu;
    #pragma unroll
    for (int o = 16; o > 0; o >>= 1) v += __shfl_down_sync(full, v, o);
    int warp = t >> 5, lane = t & 31;
    if (lane == 0) sw[warp] = v;
    __syncthreads();
    if (warp == 0) {
        float a = (lane < 16) ? sw[lane] : 0.f;
        #pragma unroll
        for (int o = 8; o > 0; o >>= 1) a += __shfl_down_sync(full, a, o);
        if (lane == 0) {
            float total = a;
            out[0] = (total == 0.f) ? 0.f : (logf(total) / (float)B);
        }
    }
}

extern "C" void kernel_launch(void* const* d_in, const int* in_sizes, int n_in,
                              void* d_out, int out_size)
{
    const float* Yp = (const float*)d_in[0];
    const float* Yg = (const float*)d_in[1];
    int B = in_sizes[0] / (LL * LL);
    if (B > MAXB) B = MAXB;

    k1_scan<<<B, 512>>>(Yp, Yg);
    k2_ratio<<<B, 256>>>(Yp);
    k3_final<<<1, 512>>>((float*)d_out, B);
}

// round 3
// speedup vs baseline: 1.0991x; 1.0991x over previous
#include <cuda_runtime.h>
#include <math.h>

#define LL 256
#define MAXB 512
#define NC 8            // chunks per sample (32 rows each)
#define CROWS 32
#define CHUNK_V4 2048   // 32*256/4 float4 per chunk

// ---- device-global scratch (allocation-free, graph-replay safe:
//      counters are reset by their last user each launch) ----
__device__ float g_psum [MAXB][NC];
__device__ float g_pgsum[MAXB][NC];
__device__ int   g_pany [MAXB][NC];
__device__ unsigned char g_rowflag[MAXB][LL];       // chunk ch owns rows [ch*32, ch*32+32)
__device__ unsigned char g_colflag[MAXB][NC][LL];
__device__ int   g_cnt[MAXB];                        // zero-init; reset by last chunk block
__device__ float g_total;                            // zero-init; reset by final block
__device__ int   g_nfin;                             // zero-init; reset by final block

__global__ void __launch_bounds__(256)
fused_loss(const float* __restrict__ Yp, const float* __restrict__ Yg,
           float* __restrict__ out, int B)
{
    const int blk = blockIdx.x;
    const int b   = blk >> 3;
    const int ch  = blk & 7;
    const int t   = threadIdx.x;
    const unsigned full = 0xffffffffu;
    const int warp = t >> 5, lane = t & 31;

    __shared__ unsigned char rflag[CROWS];
    __shared__ unsigned char cflag[LL];
    __shared__ float swp[8], swpg[8];
    __shared__ int   sanyw[8];
    __shared__ int   s_last;

    if (t < CROWS) rflag[t] = 0;
    cflag[t] = 0;
    __syncthreads();

    // ---------------- streaming phase: this chunk's 32x256 slab ----------------
    const float4* __restrict__ p4 =
        (const float4*)(Yp + (size_t)b * (LL * LL) + ch * (CROWS * LL));
    const float4* __restrict__ g4 =
        (const float4*)(Yg + (size_t)b * (LL * LL) + ch * (CROWS * LL));

    float sp = 0.f, spg = 0.f;
    int any = 0;
    #pragma unroll 4
    for (int i = t; i < CHUNK_V4; i += 256) {
        float4 v = p4[i];
        float4 g = g4[i];
        sp  += (v.x + v.y) + (v.z + v.w);
        spg += g.x * v.x + g.y * v.y + g.z * v.z + g.w * v.w;
        if (g.x > 0.f || g.y > 0.f || g.z > 0.f || g.w > 0.f) any = 1;

        bool f0 = v.x > 0.5f, f1 = v.y > 0.5f, f2 = v.z > 0.5f, f3 = v.w > 0.5f;
        if (f0 | f1 | f2 | f3) {
            int pix = i << 2;
            rflag[pix >> 8] = 1;          // row within chunk
            int c0 = pix & 255;
            if (f0) cflag[c0]     = 1;
            if (f1) cflag[c0 + 1] = 1;
            if (f2) cflag[c0 + 2] = 1;
            if (f3) cflag[c0 + 3] = 1;
        }
    }

    // block reduction (8 warps)
    #pragma unroll
    for (int o = 16; o > 0; o >>= 1) {
        sp  += __shfl_down_sync(full, sp, o);
        spg += __shfl_down_sync(full, spg, o);
    }
    any = __any_sync(full, any);
    if (lane == 0) { swp[warp] = sp; swpg[warp] = spg; sanyw[warp] = any; }
    __syncthreads();

    if (t == 0) {
        float a = 0.f, c = 0.f; int an = 0;
        #pragma unroll
        for (int w = 0; w < 8; w++) { a += swp[w]; c += swpg[w]; an |= sanyw[w]; }
        g_psum [b][ch] = a;
        g_pgsum[b][ch] = c;
        g_pany [b][ch] = an;
    }
    if (t < CROWS) g_rowflag[b][ch * CROWS + t] = rflag[t];
    g_colflag[b][ch][t] = cflag[t];
    __syncthreads();                       // all partial writes issued

    // ---------------- last chunk block of this sample finishes it -------------
    if (t == 0) {
        __threadfence();
        int c = atomicAdd(&g_cnt[b], 1);
        s_last = (c == NC - 1);
        if (s_last) {
            __threadfence();
            g_cnt[b] = 0;                  // reset for next graph replay
        }
    }
    __syncthreads();
    if (!s_last) return;

    __shared__ int sMinR, sMaxR, sMinC, sMaxC;
    __shared__ float sSum, sPos;
    __shared__ int   sAny;
    __shared__ float sw[8];

    if (t == 0) {
        sMinR = LL; sMaxR = -1; sMinC = LL; sMaxC = -1;
        float a = 0.f, c = 0.f; int an = 0;
        #pragma unroll
        for (int k = 0; k < NC; k++) { a += g_psum[b][k]; c += g_pgsum[b][k]; an |= g_pany[b][k]; }
        sSum = a; sPos = c; sAny = an;
    }
    __syncthreads();

    if (g_rowflag[b][t]) { atomicMin(&sMinR, t); atomicMax(&sMaxR, t); }
    unsigned char cf = 0;
    #pragma unroll
    for (int k = 0; k < NC; k++) cf |= g_colflag[b][k][t];
    if (cf) { atomicMin(&sMinC, t); atomicMax(&sMaxC, t); }
    __syncthreads();

    const float sumYp = sSum;
    float positive;

    if (sAny) {
        positive = sPos;
    } else {
        int left, right, up, down;
        if (sMaxR < 0) { left = 0; right = 0; }
        else           { left = sMinR; right = (LL - 1) - sMaxR; }
        if (sMaxC < 0) { up = 0; down = 0; }
        else           { up = sMinC; down = (LL - 1) - sMaxC; }
        int x_r = (right - left) >> 1;     // floor division, matches //2
        int y_r = (down  - up)   >> 1;
        float gt0 = (float)(left + x_r);   // vs column coord
        float gt1 = (float)(up   + y_r);   // vs row coord

        float acc = 0.f;
        if (x_r != 0 && y_r != 0) {
            // h>0.1  <=>  d0^4+d1^4 < ln(10)*(4/9) => |d0|,|d1| < ~1.006
            float hx = fabsf((float)x_r) * 1.01f + 1.5f;
            float hy = fabsf((float)y_r) * 1.01f + 1.5f;
            int c0 = max(0, (int)floorf(gt0 - hx));
            int c1 = min(LL - 1, (int)ceilf(gt0 + hx));
            int r0 = max(0, (int)floorf(gt1 - hy));
            int r1 = min(LL - 1, (int)ceilf(gt1 + hy));
            int W = c1 - c0 + 1;
            int n = W * (r1 - r0 + 1);
            const float denom = 0.44444445f;   // f32((2/3)^2)
            const float* __restrict__ base = Yp + (size_t)b * (LL * LL);
            for (int i = t; i < n; i += 256) {
                int r = r0 + i / W;
                int c = c0 + i % W;
                float d0 = ((float)c - gt0) / (float)x_r;
                float d1 = ((float)r - gt1) / (float)y_r;
                float d02 = d0 * d0, d12 = d1 * d1;
                float s = d02 * d02 + d12 * d12;
                float h = expf(-s / denom);
                if (h > 0.1f) acc += base[r * LL + c];
            }
        }
        #pragma unroll
        for (int o = 16; o > 0; o >>= 1) acc += __shfl_down_sync(full, acc, o);
        if (lane == 0) sw[warp] = acc;
        __syncthreads();
        float tot = 0.f;
        if (t == 0) {
            #pragma unroll
            for (int w = 0; w < 8; w++) tot += sw[w];
        }
        positive = tot;   // only thread 0's value is used below
    }

    // ---------------- global accumulation + final log by last sample ----------
    if (t == 0) {
        float negative = sumYp - positive;
        float ratio = negative / (positive + 1e-6f);
        atomicAdd(&g_total, ratio);
        __threadfence();
        int n = atomicAdd(&g_nfin, 1);
        if (n == B - 1) {
            float total = atomicExch(&g_total, 0.f);   // read + reset
            atomicExch(&g_nfin, 0);                    // reset
            out[0] = (total == 0.f) ? 0.f : (logf(total) / (float)B);
        }
    }
}

extern "C" void kernel_launch(void* const* d_in, const int* in_sizes, int n_in,
                              void* d_out, int out_size)
{
    const float* Yp = (const float*)d_in[0];
    const float* Yg = (const float*)d_in[1];
    int B = in_sizes[0] / (LL * LL);
    if (B > MAXB) B = MAXB;

    fused_loss<<<B * NC, 256>>>(Yp, Yg, (float*)d_out, B);
}